// round 2
// baseline (speedup 1.0000x reference)
#include <cuda_runtime.h>
#include <math.h>

// ---------------------------------------------------------------------------
// GQAWithKVCache: fused transformer attention block, fp32 baseline.
//   h = rmsnorm(x, g)
//   q = rope(h@wq), k = rope(h@wk), v = h@wv
//   o = causal_flash_attention(q, k, v)   (GQA: 32 q heads, 8 kv heads)
//   out = x + o@wo
// Shapes: B=1, S=2048, D_MODEL=2048, HQ=32, HKV=8, HD=64.
// ---------------------------------------------------------------------------

#define S_LEN   2048
#define DMODEL  2048
#define HQ      32
#define HKV     8
#define HD      64
#define KVDIM   (HKV * HD)   // 512

// ------------------------- scratch (no allocations) ------------------------
__device__ float g_h[S_LEN * DMODEL];   // rmsnorm output
__device__ float g_q[S_LEN * DMODEL];   // q projection (then roped)
__device__ float g_k[S_LEN * KVDIM];    // k projection (then roped)
__device__ float g_v[S_LEN * KVDIM];    // v projection
__device__ float g_o[S_LEN * DMODEL];   // attention output

// ------------------------------ RMSNorm ------------------------------------
__global__ void __launch_bounds__(256) rmsnorm_kernel(
    const float* __restrict__ x, const float* __restrict__ g,
    float* __restrict__ h) {
  int row = blockIdx.x;
  const float4* xr = (const float4*)(x + (size_t)row * DMODEL);
  float4 v0 = xr[threadIdx.x];
  float4 v1 = xr[threadIdx.x + 256];
  float ss = v0.x * v0.x + v0.y * v0.y + v0.z * v0.z + v0.w * v0.w
           + v1.x * v1.x + v1.y * v1.y + v1.z * v1.z + v1.w * v1.w;
  #pragma unroll
  for (int off = 16; off; off >>= 1) ss += __shfl_xor_sync(0xffffffffu, ss, off);
  __shared__ float warpsum[8];
  __shared__ float s_inv;
  if ((threadIdx.x & 31) == 0) warpsum[threadIdx.x >> 5] = ss;
  __syncthreads();
  if (threadIdx.x == 0) {
    float t = 0.f;
    #pragma unroll
    for (int i = 0; i < 8; i++) t += warpsum[i];
    s_inv = rsqrtf(t / (float)DMODEL + 1e-9f);
  }
  __syncthreads();
  float inv = s_inv;
  const float4* gg = (const float4*)g;
  float4* hr = (float4*)(h + (size_t)row * DMODEL);
  float4 g0 = gg[threadIdx.x];
  float4 g1 = gg[threadIdx.x + 256];
  hr[threadIdx.x]       = make_float4(v0.x * inv * g0.x, v0.y * inv * g0.y,
                                      v0.z * inv * g0.z, v0.w * inv * g0.w);
  hr[threadIdx.x + 256] = make_float4(v1.x * inv * g1.x, v1.y * inv * g1.y,
                                      v1.z * inv * g1.z, v1.w * inv * g1.w);
}

// ------------------------------- GEMM --------------------------------------
// C[M,N] = A[M,K] @ B[K,N] (+ resid).  64x64x16 tiles, 256 threads, 4x4/thread.
#define TM 64
#define TN 64
#define TK 16

__global__ void __launch_bounds__(256) gemm_kernel(
    const float* __restrict__ A, const float* __restrict__ B,
    const float* __restrict__ resid, float* __restrict__ C,
    int M, int N, int K) {
  __shared__ float As[TK][TM];   // transposed A tile
  __shared__ float Bs[TK][TN];

  int bm = blockIdx.y * TM;
  int bn = blockIdx.x * TN;
  int tid = threadIdx.x;
  int tx = tid & 15;          // 0..15 -> column group
  int ty = tid >> 4;          // 0..15 -> row group

  // A tile load indices: 64 rows x 16 cols, one float4 per thread
  int ar = tid >> 2;          // 0..63
  int ac = (tid & 3) * 4;     // 0,4,8,12
  // B tile load indices: 16 rows x 64 cols, one float4 per thread
  int br = tid >> 4;          // 0..15
  int bc = (tid & 15) * 4;    // 0..60

  float acc[4][4];
  #pragma unroll
  for (int i = 0; i < 4; i++)
    #pragma unroll
    for (int j = 0; j < 4; j++) acc[i][j] = 0.f;

  const float* Aap = A + (size_t)(bm + ar) * K + ac;
  const float* Bbp = B + (size_t)br * N + bn + bc;

  for (int k0 = 0; k0 < K; k0 += TK) {
    float4 a4 = *(const float4*)(Aap + k0);
    As[ac + 0][ar] = a4.x;
    As[ac + 1][ar] = a4.y;
    As[ac + 2][ar] = a4.z;
    As[ac + 3][ar] = a4.w;
    *(float4*)&Bs[br][bc] = *(const float4*)(Bbp + (size_t)k0 * N);
    __syncthreads();
    #pragma unroll
    for (int kk = 0; kk < TK; kk++) {
      float4 av = *(const float4*)&As[kk][ty * 4];
      float4 bv = *(const float4*)&Bs[kk][tx * 4];
      float a[4] = {av.x, av.y, av.z, av.w};
      float b[4] = {bv.x, bv.y, bv.z, bv.w};
      #pragma unroll
      for (int i = 0; i < 4; i++)
        #pragma unroll
        for (int j = 0; j < 4; j++) acc[i][j] += a[i] * b[j];
    }
    __syncthreads();
  }

  #pragma unroll
  for (int i = 0; i < 4; i++) {
    size_t off = (size_t)(bm + ty * 4 + i) * N + bn + tx * 4;
    float4 out = make_float4(acc[i][0], acc[i][1], acc[i][2], acc[i][3]);
    if (resid) {
      float4 rv = *(const float4*)(resid + off);
      out.x += rv.x; out.y += rv.y; out.z += rv.z; out.w += rv.w;
    }
    *(float4*)(C + off) = out;
  }
}

// ------------------------------- RoPE --------------------------------------
// In-place rotate-half RoPE on t: [S, H, 64]. One thread per (s, h, j<32).
__global__ void rope_kernel(float* __restrict__ t, int H, int total) {
  int idx = blockIdx.x * blockDim.x + threadIdx.x;
  if (idx >= total) return;
  int j = idx & 31;
  int tmp = idx >> 5;
  int hh = tmp % H;
  int s = tmp / H;
  // match reference: inv_freq = 10000^{-(2j)/64} in fp32; ang = s * inv_freq in fp32
  float e = (2.0f * (float)j) / 64.0f;
  float inv_freq = powf(10000.0f, -e);
  float ang = (float)s * inv_freq;
  float c, sn;
  sincosf(ang, &sn, &c);
  float* base = t + ((size_t)s * H + hh) * HD;
  float x1 = base[j];
  float x2 = base[j + 32];
  base[j]      = x1 * c - x2 * sn;
  base[j + 32] = x1 * sn + x2 * c;
}

// --------------------------- Flash attention -------------------------------
// One thread per query row; K/V tiles staged in smem (broadcast reads).
#define FA_BQ 128
#define FA_BK 32

__global__ void __launch_bounds__(FA_BQ) flash_kernel(
    const float* __restrict__ Q, const float* __restrict__ Kc,
    const float* __restrict__ Vc, float* __restrict__ O) {
  int h = blockIdx.x;                          // 0..31
  int qt = gridDim.y - 1 - blockIdx.y;         // long rows launch first
  int hk = h >> 2;                             // GROUP = 4
  int q_idx = qt * FA_BQ + threadIdx.x;

  const float4* qrow = (const float4*)(Q + (size_t)q_idx * DMODEL + h * HD);
  float q[HD];
  #pragma unroll
  for (int i = 0; i < 16; i++) {
    float4 t = qrow[i];
    q[4 * i] = t.x; q[4 * i + 1] = t.y; q[4 * i + 2] = t.z; q[4 * i + 3] = t.w;
  }
  float o[HD];
  #pragma unroll
  for (int d = 0; d < HD; d++) o[d] = 0.f;
  float m = -__int_as_float(0x7f800000);   // -inf
  float l = 0.f;

  __shared__ float Ks[FA_BK][HD];
  __shared__ float Vs[FA_BK][HD];

  int r = threadIdx.x >> 2;          // 0..31 : kv row in tile
  int c = (threadIdx.x & 3) * 16;    // 0,16,32,48
  int kv_end = (qt + 1) * FA_BQ;

  for (int kv0 = 0; kv0 < kv_end; kv0 += FA_BK) {
    __syncthreads();
    const float* kp = Kc + (size_t)(kv0 + r) * KVDIM + hk * HD + c;
    const float* vp = Vc + (size_t)(kv0 + r) * KVDIM + hk * HD + c;
    #pragma unroll
    for (int i = 0; i < 4; i++) {
      *(float4*)&Ks[r][c + 4 * i] = *(const float4*)(kp + 4 * i);
      *(float4*)&Vs[r][c + 4 * i] = *(const float4*)(vp + 4 * i);
    }
    __syncthreads();

    int nvalid = q_idx - kv0 + 1;
    if (nvalid <= 0) continue;           // reconverges at next-iter barrier
    if (nvalid > FA_BK) nvalid = FA_BK;

    float s[FA_BK];
    float mt = m;
    for (int j = 0; j < nvalid; j++) {
      float acc = 0.f;
      #pragma unroll
      for (int d4 = 0; d4 < 16; d4++) {
        float4 k4 = *(const float4*)&Ks[j][d4 * 4];
        acc += q[4 * d4] * k4.x + q[4 * d4 + 1] * k4.y
             + q[4 * d4 + 2] * k4.z + q[4 * d4 + 3] * k4.w;
      }
      s[j] = acc * 0.125f;               // 1/sqrt(64)
      mt = fmaxf(mt, s[j]);
    }
    float scale = expf(m - mt);
    m = mt;
    l *= scale;
    #pragma unroll
    for (int d = 0; d < HD; d++) o[d] *= scale;
    for (int j = 0; j < nvalid; j++) {
      float p = expf(s[j] - m);
      l += p;
      #pragma unroll
      for (int d4 = 0; d4 < 16; d4++) {
        float4 v4 = *(const float4*)&Vs[j][d4 * 4];
        o[4 * d4]     += p * v4.x;
        o[4 * d4 + 1] += p * v4.y;
        o[4 * d4 + 2] += p * v4.z;
        o[4 * d4 + 3] += p * v4.w;
      }
    }
  }

  float inv = 1.f / l;
  float4* orow = (float4*)(O + (size_t)q_idx * DMODEL + h * HD);
  #pragma unroll
  for (int i = 0; i < 16; i++)
    orow[i] = make_float4(o[4 * i] * inv, o[4 * i + 1] * inv,
                          o[4 * i + 2] * inv, o[4 * i + 3] * inv);
}

// ------------------------------ launch -------------------------------------
extern "C" void kernel_launch(void* const* d_in, const int* in_sizes, int n_in,
                              void* d_out, int out_size) {
  const float* x  = (const float*)d_in[0];
  const float* g  = (const float*)d_in[1];
  const float* wq = (const float*)d_in[2];
  const float* wk = (const float*)d_in[3];
  const float* wv = (const float*)d_in[4];
  const float* wo = (const float*)d_in[5];
  float* out = (float*)d_out;

  float *h, *q, *k, *v, *o;
  cudaGetSymbolAddress((void**)&h, g_h);
  cudaGetSymbolAddress((void**)&q, g_q);
  cudaGetSymbolAddress((void**)&k, g_k);
  cudaGetSymbolAddress((void**)&v, g_v);
  cudaGetSymbolAddress((void**)&o, g_o);

  // 1) rmsnorm
  rmsnorm_kernel<<<S_LEN, 256>>>(x, g, h);

  // 2) projections
  gemm_kernel<<<dim3(DMODEL / TN, S_LEN / TM), 256>>>(h, wq, nullptr, q,
                                                      S_LEN, DMODEL, DMODEL);
  gemm_kernel<<<dim3(KVDIM / TN, S_LEN / TM), 256>>>(h, wk, nullptr, k,
                                                     S_LEN, KVDIM, DMODEL);
  gemm_kernel<<<dim3(KVDIM / TN, S_LEN / TM), 256>>>(h, wv, nullptr, v,
                                                     S_LEN, KVDIM, DMODEL);

  // 3) rope on q and k (in place)
  {
    int totq = S_LEN * HQ * 32;
    rope_kernel<<<(totq + 255) / 256, 256>>>(q, HQ, totq);
    int totk = S_LEN * HKV * 32;
    rope_kernel<<<(totk + 255) / 256, 256>>>(k, HKV, totk);
  }

  // 4) causal flash attention (GQA)
  flash_kernel<<<dim3(HQ, S_LEN / FA_BQ), FA_BQ>>>(q, k, v, o);

  // 5) output projection + residual
  gemm_kernel<<<dim3(DMODEL / TN, S_LEN / TM), 256>>>(o, wo, x, out,
                                                      S_LEN, DMODEL, DMODEL);
}

// round 11
// speedup vs baseline: 1.6282x; 1.6282x over previous
#include <cuda_runtime.h>
#include <cuda_bf16.h>
#include <stdint.h>
#include <math.h>

// ---------------------------------------------------------------------------
// GQAWithKVCache — round 7: GEMMs on HMMA (mma.sync bf16x3), flash fp32 SIMT.
// tcgen05 is unavailable (harness lowers via .target sm_103, no 'a' features).
// Shapes: B=1, S=2048, D_MODEL=2048, HQ=32, HKV=8, HD=64.
// ---------------------------------------------------------------------------

#define S_LEN   2048
#define DMODEL  2048
#define HQ      32
#define HKV     8
#define HD      64
#define KVDIM   (HKV * HD)   // 512

// ------------------------- scratch (no allocations) ------------------------
__device__ __align__(16) __nv_bfloat16 g_h_hi[S_LEN * DMODEL];
__device__ __align__(16) __nv_bfloat16 g_h_lo[S_LEN * DMODEL];
__device__ __align__(16) __nv_bfloat16 g_wqT_hi[DMODEL * DMODEL];  // [N][K]
__device__ __align__(16) __nv_bfloat16 g_wqT_lo[DMODEL * DMODEL];
__device__ __align__(16) __nv_bfloat16 g_wkT_hi[KVDIM * DMODEL];
__device__ __align__(16) __nv_bfloat16 g_wkT_lo[KVDIM * DMODEL];
__device__ __align__(16) __nv_bfloat16 g_wvT_hi[KVDIM * DMODEL];
__device__ __align__(16) __nv_bfloat16 g_wvT_lo[KVDIM * DMODEL];
__device__ __align__(16) __nv_bfloat16 g_woT_hi[DMODEL * DMODEL];
__device__ __align__(16) __nv_bfloat16 g_woT_lo[DMODEL * DMODEL];
__device__ __align__(16) __nv_bfloat16 g_o_hi[S_LEN * DMODEL];
__device__ __align__(16) __nv_bfloat16 g_o_lo[S_LEN * DMODEL];
__device__ float g_q[S_LEN * DMODEL];
__device__ float g_k[S_LEN * KVDIM];
__device__ float g_v[S_LEN * KVDIM];

// ------------------------------ PTX helpers --------------------------------
__device__ __forceinline__ uint32_t smem_u32(const void* p) {
  uint32_t a;
  asm("{ .reg .u64 t; cvta.to.shared.u64 t, %1; cvt.u32.u64 %0, t; }"
      : "=r"(a) : "l"(p));
  return a;
}

#define SWZ128(x) ((x) ^ (((x) >> 3) & 0x70))

#define CP_ASYNC16(dst, src) \
  asm volatile("cp.async.cg.shared.global [%0], [%1], 16;" \
               :: "r"(dst), "l"(src) : "memory")
#define CP_COMMIT() asm volatile("cp.async.commit_group;" ::: "memory")
#define CP_WAIT0()  asm volatile("cp.async.wait_group 0;" ::: "memory")
#define CP_WAIT1()  asm volatile("cp.async.wait_group 1;" ::: "memory")

#define LDSM_X4(r0, r1, r2, r3, addr)                                     \
  asm volatile("ldmatrix.sync.aligned.m8n8.x4.shared.b16 {%0,%1,%2,%3}, [%4];" \
               : "=r"(r0), "=r"(r1), "=r"(r2), "=r"(r3) : "r"(addr))
#define LDSM_X2(r0, r1, addr)                                             \
  asm volatile("ldmatrix.sync.aligned.m8n8.x2.shared.b16 {%0,%1}, [%2];"  \
               : "=r"(r0), "=r"(r1) : "r"(addr))

#define MMA16816(c, a, b)                                                 \
  asm volatile(                                                           \
      "mma.sync.aligned.m16n8k16.row.col.f32.bf16.bf16.f32 "              \
      "{%0,%1,%2,%3},{%4,%5,%6,%7},{%8,%9},{%0,%1,%2,%3};"                \
      : "+f"((c)[0]), "+f"((c)[1]), "+f"((c)[2]), "+f"((c)[3])            \
      : "r"((a)[0]), "r"((a)[1]), "r"((a)[2]), "r"((a)[3]),               \
        "r"((b)[0]), "r"((b)[1]))

// ------------------------------ RMSNorm + split ----------------------------
__global__ void __launch_bounds__(256) rmsnorm_split_kernel(
    const float* __restrict__ x, const float* __restrict__ g,
    __nv_bfloat16* __restrict__ hh, __nv_bfloat16* __restrict__ hl) {
  int row = blockIdx.x;
  const float4* xr = (const float4*)(x + (size_t)row * DMODEL);
  float4 v0 = xr[threadIdx.x];
  float4 v1 = xr[threadIdx.x + 256];
  float ss = v0.x * v0.x + v0.y * v0.y + v0.z * v0.z + v0.w * v0.w
           + v1.x * v1.x + v1.y * v1.y + v1.z * v1.z + v1.w * v1.w;
  #pragma unroll
  for (int off = 16; off; off >>= 1) ss += __shfl_xor_sync(0xffffffffu, ss, off);
  __shared__ float warpsum[8];
  __shared__ float s_inv;
  if ((threadIdx.x & 31) == 0) warpsum[threadIdx.x >> 5] = ss;
  __syncthreads();
  if (threadIdx.x == 0) {
    float t = 0.f;
    #pragma unroll
    for (int i = 0; i < 8; i++) t += warpsum[i];
    s_inv = rsqrtf(t / (float)DMODEL + 1e-9f);
  }
  __syncthreads();
  float inv = s_inv;
  const float4* gg = (const float4*)g;
  float4 g0 = gg[threadIdx.x];
  float4 g1 = gg[threadIdx.x + 256];
  size_t b0 = (size_t)row * DMODEL + threadIdx.x * 4;
  size_t b1 = (size_t)row * DMODEL + (threadIdx.x + 256) * 4;
  float a0[4] = {v0.x * inv * g0.x, v0.y * inv * g0.y, v0.z * inv * g0.z, v0.w * inv * g0.w};
  float a1[4] = {v1.x * inv * g1.x, v1.y * inv * g1.y, v1.z * inv * g1.z, v1.w * inv * g1.w};
  #pragma unroll
  for (int c = 0; c < 4; c++) {
    __nv_bfloat16 hi0 = __float2bfloat16(a0[c]);
    hh[b0 + c] = hi0;
    hl[b0 + c] = __float2bfloat16(a0[c] - __bfloat162float(hi0));
    __nv_bfloat16 hi1 = __float2bfloat16(a1[c]);
    hh[b1 + c] = hi1;
    hl[b1 + c] = __float2bfloat16(a1[c] - __bfloat162float(hi1));
  }
}

// --------------------- weight transpose + bf16 split -----------------------
__global__ void __launch_bounds__(256) transpose_split_kernel(
    const float* __restrict__ w, __nv_bfloat16* __restrict__ th,
    __nv_bfloat16* __restrict__ tl, int K, int N) {
  __shared__ float t[32][33];
  int n0 = blockIdx.x * 32, k0 = blockIdx.y * 32;
  for (int j = threadIdx.y; j < 32; j += 8)
    t[j][threadIdx.x] = w[(size_t)(k0 + j) * N + n0 + threadIdx.x];
  __syncthreads();
  for (int j = threadIdx.y; j < 32; j += 8) {
    float v = t[threadIdx.x][j];
    size_t o = (size_t)(n0 + j) * K + k0 + threadIdx.x;
    __nv_bfloat16 hi = __float2bfloat16(v);
    th[o] = hi;
    tl[o] = __float2bfloat16(v - __bfloat162float(hi));
  }
}

// ----------------------- HMMA bf16x3 GEMM ----------------------------------
// C[M,N] = A[M,K] @ B^T[N,K] (+resid).
// CTA 128x128, BK=64, 8 warps (warp tile 64x32), double-buffered cp.async.
// Up to 3 column segments (different B/C) packed into one launch via grid.x.
#define MM_STAGE_BYTES 65536           // 4 tiles x 16KB (Ah, Al, Bh, Bl)
#define MM_SMEM_BYTES  (2 * MM_STAGE_BYTES + 1024)

__global__ void __launch_bounds__(256) mm_kernel(
    const __nv_bfloat16* __restrict__ Ah, const __nv_bfloat16* __restrict__ Al,
    const float* __restrict__ resid, int K,
    const __nv_bfloat16* B0h, const __nv_bfloat16* B0l, float* C0, int N0, int nb0,
    const __nv_bfloat16* B1h, const __nv_bfloat16* B1l, float* C1, int N1, int nb1,
    const __nv_bfloat16* B2h, const __nv_bfloat16* B2l, float* C2, int N2) {
  extern __shared__ char smem_raw[];
  uint32_t sb = smem_u32(smem_raw);
  uint32_t base = (sb + 1023) & ~1023u;

  int tid = threadIdx.x, lane = tid & 31, wid = tid >> 5;
  int wm = wid >> 2;       // 0..1 : 64-row slab
  int wn = wid & 3;        // 0..3 : 32-col slab

  const __nv_bfloat16 *Bh, *Bl;
  float* C;
  int N, bn;
  int bxx = blockIdx.x;
  if (bxx < nb0)                { Bh = B0h; Bl = B0l; C = C0; N = N0; bn = bxx * 128; }
  else if (bxx < nb0 + nb1)     { Bh = B1h; Bl = B1l; C = C1; N = N1; bn = (bxx - nb0) * 128; }
  else                          { Bh = B2h; Bl = B2l; C = C2; N = N2; bn = (bxx - nb0 - nb1) * 128; }
  int bm = blockIdx.y * 128;

  float acc[4][4][4];
  #pragma unroll
  for (int i = 0; i < 4; i++)
    #pragma unroll
    for (int j = 0; j < 4; j++)
      #pragma unroll
      for (int r = 0; r < 4; r++) acc[i][j][r] = 0.f;

  // per-thread load geometry (1024 16B-chunks per tile, 4 per thread)
  int l_row[4], l_ck[4];
  uint32_t l_so[4];
  #pragma unroll
  for (int i = 0; i < 4; i++) {
    int idx = i * 256 + tid;
    l_row[i] = idx >> 3;
    l_ck[i]  = idx & 7;
    l_so[i]  = SWZ128((uint32_t)(l_row[i] * 128 + l_ck[i] * 16));
  }

  const int nch = K >> 6;

  // stage tile base addresses
  auto stage_base = [&](int s) { return base + (uint32_t)s * MM_STAGE_BYTES; };

  // issue loads for chunk ch into stage s
  #define MM_LOAD(s, k0_)                                                      \
    do {                                                                       \
      uint32_t stb = stage_base(s);                                            \
      _Pragma("unroll")                                                        \
      for (int i = 0; i < 4; i++) {                                            \
        size_t ga = (size_t)(bm + l_row[i]) * K + (k0_) + l_ck[i] * 8;         \
        size_t gb = (size_t)(bn + l_row[i]) * K + (k0_) + l_ck[i] * 8;         \
        CP_ASYNC16(stb + l_so[i],         Ah + ga);                            \
        CP_ASYNC16(stb + 16384 + l_so[i], Al + ga);                            \
        CP_ASYNC16(stb + 32768 + l_so[i], Bh + gb);                            \
        CP_ASYNC16(stb + 49152 + l_so[i], Bl + gb);                            \
      }                                                                        \
    } while (0)

  MM_LOAD(0, 0);
  CP_COMMIT();

  // ldmatrix per-lane geometry
  int a_r = lane & 15;            // row within m16 tile
  int a_k = lane >> 4;            // k half (16B chunk)
  int b_r = lane & 7;             // n row within n8 tile
  int b_k = (lane >> 3) & 1;      // k half

  for (int ch = 0; ch < nch; ch++) {
    if (ch + 1 < nch) {
      MM_LOAD((ch + 1) & 1, (ch + 1) * 64);
      CP_COMMIT();
      CP_WAIT1();
    } else {
      CP_WAIT0();
    }
    __syncthreads();

    uint32_t stb = stage_base(ch & 1);
    #pragma unroll
    for (int ks = 0; ks < 4; ks++) {
      uint32_t fa_h[4][4], fa_l[4][4], fb_h[4][2], fb_l[4][2];
      #pragma unroll
      for (int mt = 0; mt < 4; mt++) {
        uint32_t off = SWZ128((uint32_t)((wm * 64 + mt * 16 + a_r) * 128 +
                                         (ks * 2 + a_k) * 16));
        LDSM_X4(fa_h[mt][0], fa_h[mt][1], fa_h[mt][2], fa_h[mt][3], stb + off);
        LDSM_X4(fa_l[mt][0], fa_l[mt][1], fa_l[mt][2], fa_l[mt][3],
                stb + 16384 + off);
      }
      #pragma unroll
      for (int nt = 0; nt < 4; nt++) {
        uint32_t off = SWZ128((uint32_t)((wn * 32 + nt * 8 + b_r) * 128 +
                                         (ks * 2 + b_k) * 16));
        LDSM_X2(fb_h[nt][0], fb_h[nt][1], stb + 32768 + off);
        LDSM_X2(fb_l[nt][0], fb_l[nt][1], stb + 49152 + off);
      }
      #pragma unroll
      for (int mt = 0; mt < 4; mt++)
        #pragma unroll
        for (int nt = 0; nt < 4; nt++) {
          MMA16816(acc[mt][nt], fa_h[mt], fb_h[nt]);
          MMA16816(acc[mt][nt], fa_l[mt], fb_h[nt]);
          MMA16816(acc[mt][nt], fa_h[mt], fb_l[nt]);
        }
    }
    __syncthreads();
  }

  // epilogue
  #pragma unroll
  for (int mt = 0; mt < 4; mt++)
    #pragma unroll
    for (int nt = 0; nt < 4; nt++) {
      int r0 = bm + wm * 64 + mt * 16 + (lane >> 2);
      int c0 = bn + wn * 32 + nt * 8 + (lane & 3) * 2;
      float2 v01 = make_float2(acc[mt][nt][0], acc[mt][nt][1]);
      float2 v23 = make_float2(acc[mt][nt][2], acc[mt][nt][3]);
      size_t o0 = (size_t)r0 * N + c0;
      size_t o1 = (size_t)(r0 + 8) * N + c0;
      if (resid) {
        float2 rv0 = *(const float2*)(resid + o0);
        float2 rv1 = *(const float2*)(resid + o1);
        v01.x += rv0.x; v01.y += rv0.y;
        v23.x += rv1.x; v23.y += rv1.y;
      }
      *(float2*)(C + o0) = v01;
      *(float2*)(C + o1) = v23;
    }
}

// ------------------------------- RoPE --------------------------------------
__global__ void rope_kernel(float* __restrict__ t, int H, int total) {
  int idx = blockIdx.x * blockDim.x + threadIdx.x;
  if (idx >= total) return;
  int j = idx & 31;
  int tmp = idx >> 5;
  int hh = tmp % H;
  int s = tmp / H;
  float e = (2.0f * (float)j) / 64.0f;
  float inv_freq = powf(10000.0f, -e);
  float ang = (float)s * inv_freq;
  float c, sn;
  sincosf(ang, &sn, &c);
  float* base = t + ((size_t)s * H + hh) * HD;
  float x1 = base[j];
  float x2 = base[j + 32];
  base[j]      = x1 * c - x2 * sn;
  base[j + 32] = x1 * sn + x2 * c;
}

// --------------------------- Flash attention -------------------------------
#define FA_BQ 128
#define FA_BK 32

__global__ void __launch_bounds__(FA_BQ) flash_kernel(
    const float* __restrict__ Q, const float* __restrict__ Kc,
    const float* __restrict__ Vc, __nv_bfloat16* __restrict__ Ohi,
    __nv_bfloat16* __restrict__ Olo) {
  int h = blockIdx.x;
  int qt = gridDim.y - 1 - blockIdx.y;
  int hk = h >> 2;
  int q_idx = qt * FA_BQ + threadIdx.x;

  const float4* qrow = (const float4*)(Q + (size_t)q_idx * DMODEL + h * HD);
  float q[HD];
  #pragma unroll
  for (int i = 0; i < 16; i++) {
    float4 t = qrow[i];
    q[4 * i] = t.x; q[4 * i + 1] = t.y; q[4 * i + 2] = t.z; q[4 * i + 3] = t.w;
  }
  float o[HD];
  #pragma unroll
  for (int d = 0; d < HD; d++) o[d] = 0.f;
  float m = -__int_as_float(0x7f800000);
  float l = 0.f;

  __shared__ float Ks[FA_BK][HD];
  __shared__ float Vs[FA_BK][HD];

  int r = threadIdx.x >> 2;
  int c = (threadIdx.x & 3) * 16;
  int kv_end = (qt + 1) * FA_BQ;

  for (int kv0 = 0; kv0 < kv_end; kv0 += FA_BK) {
    __syncthreads();
    const float* kp = Kc + (size_t)(kv0 + r) * KVDIM + hk * HD + c;
    const float* vp = Vc + (size_t)(kv0 + r) * KVDIM + hk * HD + c;
    #pragma unroll
    for (int i = 0; i < 4; i++) {
      *(float4*)&Ks[r][c + 4 * i] = *(const float4*)(kp + 4 * i);
      *(float4*)&Vs[r][c + 4 * i] = *(const float4*)(vp + 4 * i);
    }
    __syncthreads();

    int nvalid = q_idx - kv0 + 1;
    if (nvalid <= 0) continue;
    if (nvalid > FA_BK) nvalid = FA_BK;

    float s[FA_BK];
    float mt = m;
    for (int j = 0; j < nvalid; j++) {
      float acc = 0.f;
      #pragma unroll
      for (int d4 = 0; d4 < 16; d4++) {
        float4 k4 = *(const float4*)&Ks[j][d4 * 4];
        acc += q[4 * d4] * k4.x + q[4 * d4 + 1] * k4.y
             + q[4 * d4 + 2] * k4.z + q[4 * d4 + 3] * k4.w;
      }
      s[j] = acc * 0.125f;
      mt = fmaxf(mt, s[j]);
    }
    float scale = expf(m - mt);
    m = mt;
    l *= scale;
    #pragma unroll
    for (int d = 0; d < HD; d++) o[d] *= scale;
    for (int j = 0; j < nvalid; j++) {
      float p = expf(s[j] - m);
      l += p;
      #pragma unroll
      for (int d4 = 0; d4 < 16; d4++) {
        float4 v4 = *(const float4*)&Vs[j][d4 * 4];
        o[4 * d4]     += p * v4.x;
        o[4 * d4 + 1] += p * v4.y;
        o[4 * d4 + 2] += p * v4.z;
        o[4 * d4 + 3] += p * v4.w;
      }
    }
  }

  float inv = 1.f / l;
  size_t ob = (size_t)q_idx * DMODEL + h * HD;
  #pragma unroll
  for (int d = 0; d < HD; d++) {
    float val = o[d] * inv;
    __nv_bfloat16 hi = __float2bfloat16(val);
    Ohi[ob + d] = hi;
    Olo[ob + d] = __float2bfloat16(val - __bfloat162float(hi));
  }
}

// ------------------------------ launch -------------------------------------
extern "C" void kernel_launch(void* const* d_in, const int* in_sizes, int n_in,
                              void* d_out, int out_size) {
  const float* x  = (const float*)d_in[0];
  const float* g  = (const float*)d_in[1];
  const float* wq = (const float*)d_in[2];
  const float* wk = (const float*)d_in[3];
  const float* wv = (const float*)d_in[4];
  const float* wo = (const float*)d_in[5];
  float* out = (float*)d_out;

  __nv_bfloat16 *hh, *hl, *wqh, *wql, *wkh, *wkl, *wvh, *wvl, *woh, *wol, *ohi, *olo;
  float *q, *k, *v;
  cudaGetSymbolAddress((void**)&hh, g_h_hi);
  cudaGetSymbolAddress((void**)&hl, g_h_lo);
  cudaGetSymbolAddress((void**)&wqh, g_wqT_hi);
  cudaGetSymbolAddress((void**)&wql, g_wqT_lo);
  cudaGetSymbolAddress((void**)&wkh, g_wkT_hi);
  cudaGetSymbolAddress((void**)&wkl, g_wkT_lo);
  cudaGetSymbolAddress((void**)&wvh, g_wvT_hi);
  cudaGetSymbolAddress((void**)&wvl, g_wvT_lo);
  cudaGetSymbolAddress((void**)&woh, g_woT_hi);
  cudaGetSymbolAddress((void**)&wol, g_woT_lo);
  cudaGetSymbolAddress((void**)&ohi, g_o_hi);
  cudaGetSymbolAddress((void**)&olo, g_o_lo);
  cudaGetSymbolAddress((void**)&q, g_q);
  cudaGetSymbolAddress((void**)&k, g_k);
  cudaGetSymbolAddress((void**)&v, g_v);

  cudaFuncSetAttribute(mm_kernel, cudaFuncAttributeMaxDynamicSharedMemorySize,
                       MM_SMEM_BYTES);

  // weight transposes + bf16 hi/lo splits
  transpose_split_kernel<<<dim3(DMODEL / 32, DMODEL / 32), dim3(32, 8)>>>(
      wq, wqh, wql, DMODEL, DMODEL);
  transpose_split_kernel<<<dim3(KVDIM / 32, DMODEL / 32), dim3(32, 8)>>>(
      wk, wkh, wkl, DMODEL, KVDIM);
  transpose_split_kernel<<<dim3(KVDIM / 32, DMODEL / 32), dim3(32, 8)>>>(
      wv, wvh, wvl, DMODEL, KVDIM);
  transpose_split_kernel<<<dim3(DMODEL / 32, DMODEL / 32), dim3(32, 8)>>>(
      wo, woh, wol, DMODEL, DMODEL);

  // rmsnorm + split
  rmsnorm_split_kernel<<<S_LEN, 256>>>(x, g, hh, hl);

  // q/k/v projections fused into one HMMA launch (grid.x segments: 16|4|4)
  mm_kernel<<<dim3(24, S_LEN / 128), 256, MM_SMEM_BYTES>>>(
      hh, hl, nullptr, DMODEL,
      wqh, wql, q, DMODEL, 16,
      wkh, wkl, k, KVDIM, 4,
      wvh, wvl, v, KVDIM);

  // rope on q and k (in place, fp32)
  {
    int totq = S_LEN * HQ * 32;
    rope_kernel<<<(totq + 255) / 256, 256>>>(q, HQ, totq);
    int totk = S_LEN * HKV * 32;
    rope_kernel<<<(totk + 255) / 256, 256>>>(k, HKV, totk);
  }

  // causal flash attention (GQA), writes bf16 hi/lo split directly
  flash_kernel<<<dim3(HQ, S_LEN / FA_BQ), FA_BQ>>>(q, k, v, ohi, olo);

  // output projection + residual
  mm_kernel<<<dim3(16, S_LEN / 128), 256, MM_SMEM_BYTES>>>(
      ohi, olo, x, DMODEL,
      woh, wol, out, DMODEL, 16,
      nullptr, nullptr, nullptr, 0, 0,
      nullptr, nullptr, nullptr, 0);
}

// round 13
// speedup vs baseline: 3.6820x; 2.2614x over previous
#include <cuda_runtime.h>
#include <cuda_bf16.h>
#include <stdint.h>
#include <math.h>

// ---------------------------------------------------------------------------
// GQAWithKVCache — round 11: everything heavy on HMMA (mma.sync bf16x3).
//   GEMMs: bf16 hi/lo x3-product, cp.async double-buffered (validated R11).
//   Flash: NEW — HMMA for both QK^T and PV with hi/lo splits, online softmax.
// Shapes: B=1, S=2048, D_MODEL=2048, HQ=32, HKV=8, HD=64.
// ---------------------------------------------------------------------------

#define S_LEN   2048
#define DMODEL  2048
#define HQ      32
#define HKV     8
#define HD      64
#define KVDIM   (HKV * HD)   // 512

// ------------------------- scratch (no allocations) ------------------------
__device__ __align__(16) __nv_bfloat16 g_h_hi[S_LEN * DMODEL];
__device__ __align__(16) __nv_bfloat16 g_h_lo[S_LEN * DMODEL];
__device__ __align__(16) __nv_bfloat16 g_wqT_hi[DMODEL * DMODEL];  // [N][K]
__device__ __align__(16) __nv_bfloat16 g_wqT_lo[DMODEL * DMODEL];
__device__ __align__(16) __nv_bfloat16 g_wkT_hi[KVDIM * DMODEL];
__device__ __align__(16) __nv_bfloat16 g_wkT_lo[KVDIM * DMODEL];
__device__ __align__(16) __nv_bfloat16 g_wvT_hi[KVDIM * DMODEL];
__device__ __align__(16) __nv_bfloat16 g_wvT_lo[KVDIM * DMODEL];
__device__ __align__(16) __nv_bfloat16 g_woT_hi[DMODEL * DMODEL];
__device__ __align__(16) __nv_bfloat16 g_woT_lo[DMODEL * DMODEL];
__device__ __align__(16) __nv_bfloat16 g_o_hi[S_LEN * DMODEL];
__device__ __align__(16) __nv_bfloat16 g_o_lo[S_LEN * DMODEL];
__device__ float g_q[S_LEN * DMODEL];
__device__ float g_k[S_LEN * KVDIM];
__device__ float g_v[S_LEN * KVDIM];
// bf16 split operands for flash
__device__ __align__(16) __nv_bfloat16 g_qh[S_LEN * DMODEL];   // roped, *0.125
__device__ __align__(16) __nv_bfloat16 g_ql[S_LEN * DMODEL];
__device__ __align__(16) __nv_bfloat16 g_kh[S_LEN * KVDIM];    // roped
__device__ __align__(16) __nv_bfloat16 g_kl[S_LEN * KVDIM];
__device__ __align__(16) __nv_bfloat16 g_vth[KVDIM * S_LEN];   // [h][d][s]
__device__ __align__(16) __nv_bfloat16 g_vtl[KVDIM * S_LEN];

// ------------------------------ PTX helpers --------------------------------
__device__ __forceinline__ uint32_t smem_u32(const void* p) {
  uint32_t a;
  asm("{ .reg .u64 t; cvta.to.shared.u64 t, %1; cvt.u32.u64 %0, t; }"
      : "=r"(a) : "l"(p));
  return a;
}

#define SWZ128(x) ((x) ^ (((x) >> 3) & 0x70))

#define CP_ASYNC16(dst, src) \
  asm volatile("cp.async.cg.shared.global [%0], [%1], 16;" \
               :: "r"(dst), "l"(src) : "memory")
#define CP_COMMIT() asm volatile("cp.async.commit_group;" ::: "memory")
#define CP_WAIT0()  asm volatile("cp.async.wait_group 0;" ::: "memory")
#define CP_WAIT1()  asm volatile("cp.async.wait_group 1;" ::: "memory")

#define LDSM_X4(r0, r1, r2, r3, addr)                                     \
  asm volatile("ldmatrix.sync.aligned.m8n8.x4.shared.b16 {%0,%1,%2,%3}, [%4];" \
               : "=r"(r0), "=r"(r1), "=r"(r2), "=r"(r3) : "r"(addr))
#define LDSM_X2(r0, r1, addr)                                             \
  asm volatile("ldmatrix.sync.aligned.m8n8.x2.shared.b16 {%0,%1}, [%2];"  \
               : "=r"(r0), "=r"(r1) : "r"(addr))

#define MMA16816(c, a, b)                                                 \
  asm volatile(                                                           \
      "mma.sync.aligned.m16n8k16.row.col.f32.bf16.bf16.f32 "              \
      "{%0,%1,%2,%3},{%4,%5,%6,%7},{%8,%9},{%0,%1,%2,%3};"                \
      : "+f"((c)[0]), "+f"((c)[1]), "+f"((c)[2]), "+f"((c)[3])            \
      : "r"((a)[0]), "r"((a)[1]), "r"((a)[2]), "r"((a)[3]),               \
        "r"((b)[0]), "r"((b)[1]))

__device__ __forceinline__ uint32_t pack2bf(__nv_bfloat16 lo, __nv_bfloat16 hi) {
  uint16_t a = *(uint16_t*)&lo, b = *(uint16_t*)&hi;
  return (uint32_t)a | ((uint32_t)b << 16);
}

// ------------------------------ RMSNorm + split ----------------------------
__global__ void __launch_bounds__(256) rmsnorm_split_kernel(
    const float* __restrict__ x, const float* __restrict__ g,
    __nv_bfloat16* __restrict__ hh, __nv_bfloat16* __restrict__ hl) {
  int row = blockIdx.x;
  const float4* xr = (const float4*)(x + (size_t)row * DMODEL);
  float4 v0 = xr[threadIdx.x];
  float4 v1 = xr[threadIdx.x + 256];
  float ss = v0.x * v0.x + v0.y * v0.y + v0.z * v0.z + v0.w * v0.w
           + v1.x * v1.x + v1.y * v1.y + v1.z * v1.z + v1.w * v1.w;
  #pragma unroll
  for (int off = 16; off; off >>= 1) ss += __shfl_xor_sync(0xffffffffu, ss, off);
  __shared__ float warpsum[8];
  __shared__ float s_inv;
  if ((threadIdx.x & 31) == 0) warpsum[threadIdx.x >> 5] = ss;
  __syncthreads();
  if (threadIdx.x == 0) {
    float t = 0.f;
    #pragma unroll
    for (int i = 0; i < 8; i++) t += warpsum[i];
    s_inv = rsqrtf(t / (float)DMODEL + 1e-9f);
  }
  __syncthreads();
  float inv = s_inv;
  const float4* gg = (const float4*)g;
  float4 g0 = gg[threadIdx.x];
  float4 g1 = gg[threadIdx.x + 256];
  size_t b0 = (size_t)row * DMODEL + threadIdx.x * 4;
  size_t b1 = (size_t)row * DMODEL + (threadIdx.x + 256) * 4;
  float a0[4] = {v0.x * inv * g0.x, v0.y * inv * g0.y, v0.z * inv * g0.z, v0.w * inv * g0.w};
  float a1[4] = {v1.x * inv * g1.x, v1.y * inv * g1.y, v1.z * inv * g1.z, v1.w * inv * g1.w};
  #pragma unroll
  for (int c = 0; c < 4; c++) {
    __nv_bfloat16 hi0 = __float2bfloat16(a0[c]);
    hh[b0 + c] = hi0;
    hl[b0 + c] = __float2bfloat16(a0[c] - __bfloat162float(hi0));
    __nv_bfloat16 hi1 = __float2bfloat16(a1[c]);
    hh[b1 + c] = hi1;
    hl[b1 + c] = __float2bfloat16(a1[c] - __bfloat162float(hi1));
  }
}

// --------------------- weight transpose + bf16 split -----------------------
__global__ void __launch_bounds__(256) transpose_split_kernel(
    const float* __restrict__ w, __nv_bfloat16* __restrict__ th,
    __nv_bfloat16* __restrict__ tl, int K, int N) {
  __shared__ float t[32][33];
  int n0 = blockIdx.x * 32, k0 = blockIdx.y * 32;
  for (int j = threadIdx.y; j < 32; j += 8)
    t[j][threadIdx.x] = w[(size_t)(k0 + j) * N + n0 + threadIdx.x];
  __syncthreads();
  for (int j = threadIdx.y; j < 32; j += 8) {
    float v = t[threadIdx.x][j];
    size_t o = (size_t)(n0 + j) * K + k0 + threadIdx.x;
    __nv_bfloat16 hi = __float2bfloat16(v);
    th[o] = hi;
    tl[o] = __float2bfloat16(v - __bfloat162float(hi));
  }
}

// ----------------------- HMMA bf16x3 GEMM (validated R11) ------------------
#define MM_STAGE_BYTES 65536
#define MM_SMEM_BYTES  (2 * MM_STAGE_BYTES + 1024)

__global__ void __launch_bounds__(256) mm_kernel(
    const __nv_bfloat16* __restrict__ Ah, const __nv_bfloat16* __restrict__ Al,
    const float* __restrict__ resid, int K,
    const __nv_bfloat16* B0h, const __nv_bfloat16* B0l, float* C0, int N0, int nb0,
    const __nv_bfloat16* B1h, const __nv_bfloat16* B1l, float* C1, int N1, int nb1,
    const __nv_bfloat16* B2h, const __nv_bfloat16* B2l, float* C2, int N2) {
  extern __shared__ char smem_raw[];
  uint32_t sb = smem_u32(smem_raw);
  uint32_t base = (sb + 1023) & ~1023u;

  int tid = threadIdx.x, lane = tid & 31, wid = tid >> 5;
  int wm = wid >> 2;
  int wn = wid & 3;

  const __nv_bfloat16 *Bh, *Bl;
  float* C;
  int N, bn;
  int bxx = blockIdx.x;
  if (bxx < nb0)                { Bh = B0h; Bl = B0l; C = C0; N = N0; bn = bxx * 128; }
  else if (bxx < nb0 + nb1)     { Bh = B1h; Bl = B1l; C = C1; N = N1; bn = (bxx - nb0) * 128; }
  else                          { Bh = B2h; Bl = B2l; C = C2; N = N2; bn = (bxx - nb0 - nb1) * 128; }
  int bm = blockIdx.y * 128;

  float acc[4][4][4];
  #pragma unroll
  for (int i = 0; i < 4; i++)
    #pragma unroll
    for (int j = 0; j < 4; j++)
      #pragma unroll
      for (int r = 0; r < 4; r++) acc[i][j][r] = 0.f;

  int l_row[4], l_ck[4];
  uint32_t l_so[4];
  #pragma unroll
  for (int i = 0; i < 4; i++) {
    int idx = i * 256 + tid;
    l_row[i] = idx >> 3;
    l_ck[i]  = idx & 7;
    l_so[i]  = SWZ128((uint32_t)(l_row[i] * 128 + l_ck[i] * 16));
  }

  const int nch = K >> 6;
  auto stage_base = [&](int s) { return base + (uint32_t)s * MM_STAGE_BYTES; };

  #define MM_LOAD(s, k0_)                                                      \
    do {                                                                       \
      uint32_t stb = stage_base(s);                                            \
      _Pragma("unroll")                                                        \
      for (int i = 0; i < 4; i++) {                                            \
        size_t ga = (size_t)(bm + l_row[i]) * K + (k0_) + l_ck[i] * 8;         \
        size_t gb = (size_t)(bn + l_row[i]) * K + (k0_) + l_ck[i] * 8;         \
        CP_ASYNC16(stb + l_so[i],         Ah + ga);                            \
        CP_ASYNC16(stb + 16384 + l_so[i], Al + ga);                            \
        CP_ASYNC16(stb + 32768 + l_so[i], Bh + gb);                            \
        CP_ASYNC16(stb + 49152 + l_so[i], Bl + gb);                            \
      }                                                                        \
    } while (0)

  MM_LOAD(0, 0);
  CP_COMMIT();

  int a_r = lane & 15;
  int a_k = lane >> 4;
  int b_r = lane & 7;
  int b_k = (lane >> 3) & 1;

  for (int ch = 0; ch < nch; ch++) {
    if (ch + 1 < nch) {
      MM_LOAD((ch + 1) & 1, (ch + 1) * 64);
      CP_COMMIT();
      CP_WAIT1();
    } else {
      CP_WAIT0();
    }
    __syncthreads();

    uint32_t stb = stage_base(ch & 1);
    #pragma unroll
    for (int ks = 0; ks < 4; ks++) {
      uint32_t fa_h[4][4], fa_l[4][4], fb_h[4][2], fb_l[4][2];
      #pragma unroll
      for (int mt = 0; mt < 4; mt++) {
        uint32_t off = SWZ128((uint32_t)((wm * 64 + mt * 16 + a_r) * 128 +
                                         (ks * 2 + a_k) * 16));
        LDSM_X4(fa_h[mt][0], fa_h[mt][1], fa_h[mt][2], fa_h[mt][3], stb + off);
        LDSM_X4(fa_l[mt][0], fa_l[mt][1], fa_l[mt][2], fa_l[mt][3],
                stb + 16384 + off);
      }
      #pragma unroll
      for (int nt = 0; nt < 4; nt++) {
        uint32_t off = SWZ128((uint32_t)((wn * 32 + nt * 8 + b_r) * 128 +
                                         (ks * 2 + b_k) * 16));
        LDSM_X2(fb_h[nt][0], fb_h[nt][1], stb + 32768 + off);
        LDSM_X2(fb_l[nt][0], fb_l[nt][1], stb + 49152 + off);
      }
      #pragma unroll
      for (int mt = 0; mt < 4; mt++)
        #pragma unroll
        for (int nt = 0; nt < 4; nt++) {
          MMA16816(acc[mt][nt], fa_h[mt], fb_h[nt]);
          MMA16816(acc[mt][nt], fa_l[mt], fb_h[nt]);
          MMA16816(acc[mt][nt], fa_h[mt], fb_l[nt]);
        }
    }
    __syncthreads();
  }

  #pragma unroll
  for (int mt = 0; mt < 4; mt++)
    #pragma unroll
    for (int nt = 0; nt < 4; nt++) {
      int r0 = bm + wm * 64 + mt * 16 + (lane >> 2);
      int c0 = bn + wn * 32 + nt * 8 + (lane & 3) * 2;
      float2 v01 = make_float2(acc[mt][nt][0], acc[mt][nt][1]);
      float2 v23 = make_float2(acc[mt][nt][2], acc[mt][nt][3]);
      size_t o0 = (size_t)r0 * N + c0;
      size_t o1 = (size_t)(r0 + 8) * N + c0;
      if (resid) {
        float2 rv0 = *(const float2*)(resid + o0);
        float2 rv1 = *(const float2*)(resid + o1);
        v01.x += rv0.x; v01.y += rv0.y;
        v23.x += rv1.x; v23.y += rv1.y;
      }
      *(float2*)(C + o0) = v01;
      *(float2*)(C + o1) = v23;
    }
}

// ------------------- RoPE + bf16 hi/lo split (q and k) ---------------------
// t: [S][H][64] fp32 -> hi/lo bf16 (rotated, * scale).
__global__ void rope_split_kernel(const float* __restrict__ src,
                                  __nv_bfloat16* __restrict__ hi,
                                  __nv_bfloat16* __restrict__ lo,
                                  int H, float scale, int total) {
  int idx = blockIdx.x * blockDim.x + threadIdx.x;
  if (idx >= total) return;
  int j = idx & 31;
  int tmp = idx >> 5;
  int hh = tmp % H;
  int s = tmp / H;
  float e = (2.0f * (float)j) / 64.0f;
  float inv_freq = powf(10000.0f, -e);
  float ang = (float)s * inv_freq;
  float c, sn;
  sincosf(ang, &sn, &c);
  size_t base = ((size_t)s * H + hh) * HD;
  float x1 = src[base + j];
  float x2 = src[base + j + 32];
  float y1 = (x1 * c - x2 * sn) * scale;
  float y2 = (x1 * sn + x2 * c) * scale;
  __nv_bfloat16 h1 = __float2bfloat16(y1);
  hi[base + j] = h1;
  lo[base + j] = __float2bfloat16(y1 - __bfloat162float(h1));
  __nv_bfloat16 h2 = __float2bfloat16(y2);
  hi[base + j + 32] = h2;
  lo[base + j + 32] = __float2bfloat16(y2 - __bfloat162float(h2));
}

// ------------- V split + transpose: [S][8][64] -> [8][64][S] bf16 ----------
__global__ void __launch_bounds__(256) split_vT_kernel(
    const float* __restrict__ v, __nv_bfloat16* __restrict__ th,
    __nv_bfloat16* __restrict__ tl) {
  __shared__ float t[32][33];
  int s0 = blockIdx.x * 32, d0 = blockIdx.y * 32, h = blockIdx.z;
  for (int j = threadIdx.y; j < 32; j += 8)
    t[j][threadIdx.x] = v[((size_t)(s0 + j) * HKV + h) * HD + d0 + threadIdx.x];
  __syncthreads();
  for (int j = threadIdx.y; j < 32; j += 8) {
    float val = t[threadIdx.x][j];
    size_t o = ((size_t)h * HD + d0 + j) * S_LEN + s0 + threadIdx.x;
    __nv_bfloat16 hi = __float2bfloat16(val);
    th[o] = hi;
    tl[o] = __float2bfloat16(val - __bfloat162float(hi));
  }
}

// --------------------- Flash attention on HMMA -----------------------------
// CTA: (head, 64-q-row tile). 4 warps x 16 rows. K/V 64x64 tiles, 2 stages.
// smem: Qh@0, Ql@8K, stage s@16K+32K*s: {Kh, Kl, Vth, Vtl} x 8KB.
#define FLASH_SMEM (16384 + 2 * 32768 + 1024)

__global__ void __launch_bounds__(128) flash_hmma_kernel(
    const __nv_bfloat16* __restrict__ qh, const __nv_bfloat16* __restrict__ ql,
    const __nv_bfloat16* __restrict__ kh, const __nv_bfloat16* __restrict__ kl,
    const __nv_bfloat16* __restrict__ vth, const __nv_bfloat16* __restrict__ vtl,
    __nv_bfloat16* __restrict__ Ohi, __nv_bfloat16* __restrict__ Olo) {
  extern __shared__ char smem_raw[];
  uint32_t sb = smem_u32(smem_raw);
  uint32_t base = (sb + 1023) & ~1023u;

  int tid = threadIdx.x, lane = tid & 31, wid = tid >> 5;
  int h = blockIdx.x;
  int qt = gridDim.y - 1 - blockIdx.y;     // heavy tiles first
  int hk = h >> 2;
  int q0 = qt * 64;

  // Q tile (hi/lo), 4 x 16B chunks per thread per tile
  #pragma unroll
  for (int i = 0; i < 4; i++) {
    int idx = i * 128 + tid;
    int row = idx >> 3, ck = idx & 7;
    uint32_t so = SWZ128((uint32_t)(row * 128 + ck * 16));
    size_t gq = ((size_t)(q0 + row) * HQ + h) * HD + ck * 8;
    CP_ASYNC16(base + so, qh + gq);
    CP_ASYNC16(base + 8192 + so, ql + gq);
  }

  #define FL_LOAD(s, k0_)                                                     \
    do {                                                                      \
      uint32_t stb = base + 16384 + (uint32_t)(s) * 32768;                    \
      _Pragma("unroll")                                                       \
      for (int i = 0; i < 4; i++) {                                           \
        int idx = i * 128 + tid;                                              \
        int row = idx >> 3, ck = idx & 7;                                     \
        uint32_t so = SWZ128((uint32_t)(row * 128 + ck * 16));                \
        size_t gk = ((size_t)((k0_) + row) * HKV + hk) * HD + ck * 8;         \
        size_t gv = ((size_t)hk * HD + row) * S_LEN + (k0_) + ck * 8;         \
        CP_ASYNC16(stb + so, kh + gk);                                        \
        CP_ASYNC16(stb + 8192 + so, kl + gk);                                 \
        CP_ASYNC16(stb + 16384 + so, vth + gv);                               \
        CP_ASYNC16(stb + 24576 + so, vtl + gv);                               \
      }                                                                       \
    } while (0)

  FL_LOAD(0, 0);
  CP_COMMIT();

  int a_r = lane & 15, a_k = lane >> 4;
  int b_r = lane & 7, b_k = (lane >> 3) & 1;
  int r_in8 = lane >> 2;
  int c2 = (lane & 3) * 2;

  uint32_t qfh[4][4], qfl[4][4];
  float oacc[8][4];
  #pragma unroll
  for (int i = 0; i < 8; i++)
    #pragma unroll
    for (int j = 0; j < 4; j++) oacc[i][j] = 0.f;
  const float NEG_INF = __int_as_float(0xff800000);
  float m0 = NEG_INF, m1 = NEG_INF, l0 = 0.f, l1 = 0.f;

  for (int kt = 0; kt <= qt; kt++) {
    if (kt + 1 <= qt) {
      FL_LOAD((kt + 1) & 1, (kt + 1) * 64);
      CP_COMMIT();
      CP_WAIT1();
    } else {
      CP_WAIT0();
    }
    __syncthreads();
    uint32_t stb = base + 16384 + (uint32_t)(kt & 1) * 32768;

    if (kt == 0) {   // Q fragments, loaded once (same commit group as stage 0)
      #pragma unroll
      for (int ks = 0; ks < 4; ks++) {
        uint32_t off = SWZ128((uint32_t)((wid * 16 + a_r) * 128 +
                                         (ks * 2 + a_k) * 16));
        LDSM_X4(qfh[ks][0], qfh[ks][1], qfh[ks][2], qfh[ks][3], base + off);
        LDSM_X4(qfl[ks][0], qfl[ks][1], qfl[ks][2], qfl[ks][3],
                base + 8192 + off);
      }
    }

    // ---- S = Q K^T (x3 split), 16x64 per warp -----------------------------
    float sacc[8][4];
    #pragma unroll
    for (int i = 0; i < 8; i++)
      #pragma unroll
      for (int j = 0; j < 4; j++) sacc[i][j] = 0.f;

    #pragma unroll
    for (int ks = 0; ks < 4; ks++)
      #pragma unroll
      for (int nt = 0; nt < 8; nt++) {
        uint32_t off = SWZ128((uint32_t)((nt * 8 + b_r) * 128 +
                                         (ks * 2 + b_k) * 16));
        uint32_t kbh[2], kbl[2];
        LDSM_X2(kbh[0], kbh[1], stb + off);
        LDSM_X2(kbl[0], kbl[1], stb + 8192 + off);
        MMA16816(sacc[nt], qfh[ks], kbh);
        MMA16816(sacc[nt], qfl[ks], kbh);
        MMA16816(sacc[nt], qfh[ks], kbl);
      }

    int r0 = q0 + wid * 16 + r_in8;
    int r1 = r0 + 8;
    if (kt == qt) {    // causal mask on diagonal tile
      #pragma unroll
      for (int nt = 0; nt < 8; nt++) {
        int cg = kt * 64 + nt * 8 + c2;
        if (cg > r0)     sacc[nt][0] = NEG_INF;
        if (cg + 1 > r0) sacc[nt][1] = NEG_INF;
        if (cg > r1)     sacc[nt][2] = NEG_INF;
        if (cg + 1 > r1) sacc[nt][3] = NEG_INF;
      }
    }

    // ---- online softmax ---------------------------------------------------
    float mx0 = m0, mx1 = m1;
    #pragma unroll
    for (int nt = 0; nt < 8; nt++) {
      mx0 = fmaxf(mx0, fmaxf(sacc[nt][0], sacc[nt][1]));
      mx1 = fmaxf(mx1, fmaxf(sacc[nt][2], sacc[nt][3]));
    }
    mx0 = fmaxf(mx0, __shfl_xor_sync(0xffffffffu, mx0, 1));
    mx0 = fmaxf(mx0, __shfl_xor_sync(0xffffffffu, mx0, 2));
    mx1 = fmaxf(mx1, __shfl_xor_sync(0xffffffffu, mx1, 1));
    mx1 = fmaxf(mx1, __shfl_xor_sync(0xffffffffu, mx1, 2));
    float sc0 = __expf(m0 - mx0), sc1 = __expf(m1 - mx1);
    m0 = mx0; m1 = mx1;

    uint32_t pAh[16], pAl[16];
    float rs0 = 0.f, rs1 = 0.f;
    #pragma unroll
    for (int nt = 0; nt < 8; nt++) {
      float p0 = __expf(sacc[nt][0] - m0);
      float p1 = __expf(sacc[nt][1] - m0);
      float p2 = __expf(sacc[nt][2] - m1);
      float p3 = __expf(sacc[nt][3] - m1);
      rs0 += p0 + p1;
      rs1 += p2 + p3;
      __nv_bfloat16 b0 = __float2bfloat16(p0), b1 = __float2bfloat16(p1);
      __nv_bfloat16 b2 = __float2bfloat16(p2), b3 = __float2bfloat16(p3);
      pAh[nt * 2]     = pack2bf(b0, b1);
      pAh[nt * 2 + 1] = pack2bf(b2, b3);
      pAl[nt * 2]     = pack2bf(__float2bfloat16(p0 - __bfloat162float(b0)),
                                __float2bfloat16(p1 - __bfloat162float(b1)));
      pAl[nt * 2 + 1] = pack2bf(__float2bfloat16(p2 - __bfloat162float(b2)),
                                __float2bfloat16(p3 - __bfloat162float(b3)));
    }
    rs0 += __shfl_xor_sync(0xffffffffu, rs0, 1);
    rs0 += __shfl_xor_sync(0xffffffffu, rs0, 2);
    rs1 += __shfl_xor_sync(0xffffffffu, rs1, 1);
    rs1 += __shfl_xor_sync(0xffffffffu, rs1, 2);
    l0 = l0 * sc0 + rs0;
    l1 = l1 * sc1 + rs1;
    #pragma unroll
    for (int nt = 0; nt < 8; nt++) {
      oacc[nt][0] *= sc0; oacc[nt][1] *= sc0;
      oacc[nt][2] *= sc1; oacc[nt][3] *= sc1;
    }

    // ---- O += P V (x3 split); A-frag direct from S acc layout -------------
    #pragma unroll
    for (int ksp = 0; ksp < 4; ksp++)
      #pragma unroll
      for (int ntd = 0; ntd < 8; ntd++) {
        uint32_t off = SWZ128((uint32_t)((ntd * 8 + b_r) * 128 +
                                         (ksp * 2 + b_k) * 16));
        uint32_t vbh[2], vbl[2];
        LDSM_X2(vbh[0], vbh[1], stb + 16384 + off);
        LDSM_X2(vbl[0], vbl[1], stb + 24576 + off);
        MMA16816(oacc[ntd], &pAh[4 * ksp], vbh);
        MMA16816(oacc[ntd], &pAl[4 * ksp], vbh);
        MMA16816(oacc[ntd], &pAh[4 * ksp], vbl);
      }
    __syncthreads();
  }

  // ---- epilogue: normalize, split to bf16 hi/lo, store --------------------
  float inv0 = 1.f / l0, inv1 = 1.f / l1;
  int r0 = q0 + wid * 16 + r_in8;
  #pragma unroll
  for (int ntd = 0; ntd < 8; ntd++) {
    int col = h * HD + ntd * 8 + c2;
    float v00 = oacc[ntd][0] * inv0, v01 = oacc[ntd][1] * inv0;
    float v10 = oacc[ntd][2] * inv1, v11 = oacc[ntd][3] * inv1;
    __nv_bfloat16 h00 = __float2bfloat16(v00), h01 = __float2bfloat16(v01);
    __nv_bfloat16 h10 = __float2bfloat16(v10), h11 = __float2bfloat16(v11);
    size_t o0 = (size_t)r0 * DMODEL + col;
    size_t o1 = (size_t)(r0 + 8) * DMODEL + col;
    *(uint32_t*)(Ohi + o0) = pack2bf(h00, h01);
    *(uint32_t*)(Ohi + o1) = pack2bf(h10, h11);
    *(uint32_t*)(Olo + o0) =
        pack2bf(__float2bfloat16(v00 - __bfloat162float(h00)),
                __float2bfloat16(v01 - __bfloat162float(h01)));
    *(uint32_t*)(Olo + o1) =
        pack2bf(__float2bfloat16(v10 - __bfloat162float(h10)),
                __float2bfloat16(v11 - __bfloat162float(h11)));
  }
}

// ------------------------------ launch -------------------------------------
extern "C" void kernel_launch(void* const* d_in, const int* in_sizes, int n_in,
                              void* d_out, int out_size) {
  const float* x  = (const float*)d_in[0];
  const float* g  = (const float*)d_in[1];
  const float* wq = (const float*)d_in[2];
  const float* wk = (const float*)d_in[3];
  const float* wv = (const float*)d_in[4];
  const float* wo = (const float*)d_in[5];
  float* out = (float*)d_out;

  __nv_bfloat16 *hh, *hl, *wqh, *wql, *wkh, *wkl, *wvh, *wvl, *woh, *wol;
  __nv_bfloat16 *ohi, *olo, *qhp, *qlp, *khp, *klp, *vth, *vtl;
  float *q, *k, *v;
  cudaGetSymbolAddress((void**)&hh, g_h_hi);
  cudaGetSymbolAddress((void**)&hl, g_h_lo);
  cudaGetSymbolAddress((void**)&wqh, g_wqT_hi);
  cudaGetSymbolAddress((void**)&wql, g_wqT_lo);
  cudaGetSymbolAddress((void**)&wkh, g_wkT_hi);
  cudaGetSymbolAddress((void**)&wkl, g_wkT_lo);
  cudaGetSymbolAddress((void**)&wvh, g_wvT_hi);
  cudaGetSymbolAddress((void**)&wvl, g_wvT_lo);
  cudaGetSymbolAddress((void**)&woh, g_woT_hi);
  cudaGetSymbolAddress((void**)&wol, g_woT_lo);
  cudaGetSymbolAddress((void**)&ohi, g_o_hi);
  cudaGetSymbolAddress((void**)&olo, g_o_lo);
  cudaGetSymbolAddress((void**)&qhp, g_qh);
  cudaGetSymbolAddress((void**)&qlp, g_ql);
  cudaGetSymbolAddress((void**)&khp, g_kh);
  cudaGetSymbolAddress((void**)&klp, g_kl);
  cudaGetSymbolAddress((void**)&vth, g_vth);
  cudaGetSymbolAddress((void**)&vtl, g_vtl);
  cudaGetSymbolAddress((void**)&q, g_q);
  cudaGetSymbolAddress((void**)&k, g_k);
  cudaGetSymbolAddress((void**)&v, g_v);

  cudaFuncSetAttribute(mm_kernel, cudaFuncAttributeMaxDynamicSharedMemorySize,
                       MM_SMEM_BYTES);
  cudaFuncSetAttribute(flash_hmma_kernel,
                       cudaFuncAttributeMaxDynamicSharedMemorySize, FLASH_SMEM);

  // weight transposes + bf16 hi/lo splits
  transpose_split_kernel<<<dim3(DMODEL / 32, DMODEL / 32), dim3(32, 8)>>>(
      wq, wqh, wql, DMODEL, DMODEL);
  transpose_split_kernel<<<dim3(KVDIM / 32, DMODEL / 32), dim3(32, 8)>>>(
      wk, wkh, wkl, DMODEL, KVDIM);
  transpose_split_kernel<<<dim3(KVDIM / 32, DMODEL / 32), dim3(32, 8)>>>(
      wv, wvh, wvl, DMODEL, KVDIM);
  transpose_split_kernel<<<dim3(DMODEL / 32, DMODEL / 32), dim3(32, 8)>>>(
      wo, woh, wol, DMODEL, DMODEL);

  // rmsnorm + split
  rmsnorm_split_kernel<<<S_LEN, 256>>>(x, g, hh, hl);

  // q/k/v projections (one fused HMMA launch: 16|4|4 column segments)
  mm_kernel<<<dim3(24, S_LEN / 128), 256, MM_SMEM_BYTES>>>(
      hh, hl, nullptr, DMODEL,
      wqh, wql, q, DMODEL, 16,
      wkh, wkl, k, KVDIM, 4,
      wvh, wvl, v, KVDIM);

  // rope + split (q scaled by 1/sqrt(64)=0.125, exact), v split+transpose
  {
    int totq = S_LEN * HQ * 32;
    rope_split_kernel<<<(totq + 255) / 256, 256>>>(q, qhp, qlp, HQ, 0.125f, totq);
    int totk = S_LEN * HKV * 32;
    rope_split_kernel<<<(totk + 255) / 256, 256>>>(k, khp, klp, HKV, 1.0f, totk);
    split_vT_kernel<<<dim3(S_LEN / 32, HD / 32, HKV), dim3(32, 8)>>>(v, vth, vtl);
  }

  // causal flash attention on HMMA (GQA), writes bf16 hi/lo split
  flash_hmma_kernel<<<dim3(HQ, S_LEN / 64), 128, FLASH_SMEM>>>(
      qhp, qlp, khp, klp, vth, vtl, ohi, olo);

  // output projection + residual
  mm_kernel<<<dim3(16, S_LEN / 128), 256, MM_SMEM_BYTES>>>(
      ohi, olo, x, DMODEL,
      woh, wol, out, DMODEL, 16,
      nullptr, nullptr, nullptr, 0, 0,
      nullptr, nullptr, nullptr, 0);
}